// round 16
// baseline (speedup 1.0000x reference)
#include <cuda_runtime.h>
#include <cstdint>

// Shapes (fixed):
//   log_probs: (128, 64) f32 | ref: (256, 128) i32 | hyp: (256, 128, 64) i32
#define NBATCH 128
#define NSAMP  64
#define NSEQ   (NBATCH * NSAMP)   // 8192
#define RLEN   256
#define HLEN   256
#define SYMS   1024               // tokens in [0,1000); slots 1000..1023 stay zero
#define SENT   1023               // sentinel token: Peq row all-zero -> state fixed point
#define TPD    4                  // token prefetch ring depth
#define CH     16                 // carry hand-off chunk (bits per packed word)
#define NLC    (HLEN / CH)        // 16 active chunks per lane
#define NCHUNK (NLC + 3)          // 19 chunk-times: +3 of pipeline skew (4 lanes)

typedef unsigned long long ull;

__device__ double   d_partial[NBATCH];
__device__ unsigned d_ticket;      // zero at start; winner resets each run

// ---------------------------------------------------------------------------
// Quad-split Myers: lane w (0..3 within a width-4 shuffle group) owns ref
// word w and runs w chunk-times behind lane w-1. Each lane packs its per-step
// carry-outs (funnelshift, 1 op/step/word); at every chunk boundary one
// width-4 shuffle hands 16 carry bits down the chain — the per-step critical
// path contains NO shuffles (R7's failure mode). Warm-up/tail are branchless:
// sentinel token gives Eq=0, and with zero carry-ins the state (Pv=~0,Mv=0)
// is a fixed point; 'act' masks carry-ins (warm-up) and score drift (tail).
// Lane bsel's word carries the score bit; other lanes' scores are discarded.
// ---------------------------------------------------------------------------
template<bool TOP>
__device__ __forceinline__ int quad_run(const ull* __restrict__ sPeq,
                                        const int* __restrict__ hyp,
                                        int n, int w, int pm) {
    ull Pv = ~0ull, Mv = 0ull;
    unsigned pw_prod = 0u, mw_prod = 0u;
    int score = 0, scoreF = 0, done = 0;

    int hh = -CH * w;                    // this lane's current step index

    auto ldtok = [&](int i) -> int {     // sentinel outside [0,HLEN)
        int t = hyp[(size_t)(i & (HLEN - 1)) * NSEQ + n];
        return ((unsigned)i < (unsigned)HLEN) ? t : SENT;
    };
    int toks[TPD];
    int tcur = ldtok(hh);
    #pragma unroll
    for (int k = 0; k < TPD; ++k) toks[k] = ldtok(hh + 1 + k);

    ull E = sPeq[(tcur << 2) + w];

    #pragma unroll 1
    for (int T = 0; T < NCHUNK; ++T) {
        // chunk-boundary exchange: lane w gets lane w-1's last-chunk carries
        unsigned pw_in = __shfl_up_sync(0xffffffffu, pw_prod >> (32 - CH), 1, 4);
        unsigned mw_in = __shfl_up_sync(0xffffffffu, mw_prod >> (32 - CH), 1, 4);
        const int  c   = T - w;                       // this lane's chunk index
        const bool act = ((unsigned)c < (unsigned)NLC);
        unsigned pw_use = (w == 0) ? 0xffffu : (act ? pw_in : 0u);
        unsigned mw_use = (w == 0) ? 0u      : (act ? mw_in : 0u);
        pw_prod = 0u; mw_prod = 0u;

        #pragma unroll
        for (int j = 0; j < CH; ++j) {
            const int t1 = toks[0];
            ull N = sPeq[(t1 << 2) + w];

            // ring rotate + refill (renamed under full unroll)
            #pragma unroll
            for (int k = 0; k < TPD - 1; ++k) toks[k] = toks[k + 1];
            toks[TPD - 1] = ldtok(hh + 1 + TPD);

            ull phin = (ull)(pw_use & 1u); pw_use >>= 1;
            ull mhin = (ull)(mw_use & 1u); mw_use >>= 1;

            ull Eq = E;
            ull Xv = Eq | Mv;
            Eq |= mhin;
            ull Xh = (((Eq & Pv) + Pv) ^ Pv) | Eq;
            ull Ph = Mv | ~(Xh | Pv);
            ull Mh = Pv & Xh;
            unsigned po = (unsigned)(Ph >> 63);
            unsigned mo = (unsigned)(Mh >> 63);
            pw_prod = __funnelshift_r(pw_prod, po, 1);   // pack carry-outs
            mw_prod = __funnelshift_r(mw_prod, mo, 1);

            int d;
            if (TOP) d = (int)po - (int)mo;              // pm==63 fast path
            else     d = (int)((Ph >> pm) & 1ull) - (int)((Mh >> pm) & 1ull);
            score += act ? d : 0;                        // mask tail drift

            Ph = (Ph << 1) | phin;
            Mh = (Mh << 1) | mhin;
            Pv = Mh | ~(Xv | Ph);
            Mv = Ph & Xv;

            // EOS capture (sentinel never triggers; warm-up is sentinel-only)
            const int isEos = (tcur == 0);
            scoreF = (isEos & ~done) ? score : scoreF;
            done  |= isEos;

            tcur = t1;
            E = N;
            ++hh;
        }
    }
    return done ? scoreF : score;
}

// ---------------------------------------------------------------------------
// Fused kernel: block b = batch row b, 256 threads = 64 samples x 4 lanes.
// 8 warps/block -> 2 warps on every SMSP (latency cover + full alu dispatch).
// ---------------------------------------------------------------------------
__global__ void __launch_bounds__(256, 1)
mer_loss_kernel(const int* __restrict__ hyp,
                const int* __restrict__ ref,
                const float* __restrict__ logp,
                float* __restrict__ out) {
    __shared__ ull    sPeq[SYMS * 4];   // 32 KB bitmask table
    __shared__ int    sMinEos;
    __shared__ float  sEr[NSAMP];
    __shared__ bool   sLast;
    __shared__ double sSum[NBATCH];

    const int b   = blockIdx.x;
    const int tid = threadIdx.x;        // 0..255
    const int q   = tid >> 2;           // sample 0..63
    const int w   = tid & 3;            // lane role: ref word w
    const int n   = b * NSAMP + q;

    // ---- build Peq in SMEM (tid == ref position j) ----
    if (tid == 0) sMinEos = RLEN;
    #pragma unroll
    for (int i = tid; i < SYMS * 4; i += 256) sPeq[i] = 0ull;
    __syncthreads();
    int rt = ref[(size_t)tid * NBATCH + b];
    if (rt == 0) atomicMin(&sMinEos, tid);
    __syncthreads();
    const int m = (sMinEos < RLEN) ? (sMinEos + 1) : RLEN;  // INCLUDE_EOS
    if (tid < m)
        atomicOr(&sPeq[(rt << 2) + (tid >> 6)], 1ull << (tid & 63));
    __syncthreads();

    const int bsel = (m - 1) >> 6;
    const int pm   = (m - 1) & 63;

    // ---- Myers DP: every lane runs its word; lane bsel owns the score ----
    int sdel;
    if (pm == 63) sdel = quad_run<true >(sPeq, hyp, n, w, pm);
    else          sdel = quad_run<false>(sPeq, hyp, n, w, pm);

    if (w == bsel) sEr[q] = (float)(m + sdel) / (float)m;
    __syncthreads();

    // ---- per-batch softmax-weighted centered reduction (warp 0) ----
    if (tid < 32) {
        int lane = tid, base = b * NSAMP;
        float er0 = sEr[lane],         er1 = sEr[lane + 32];
        float lp0 = logp[base + lane], lp1 = logp[base + 32 + lane];

        float mx = fmaxf(lp0, lp1);
        #pragma unroll
        for (int o = 16; o; o >>= 1) mx = fmaxf(mx, __shfl_xor_sync(0xffffffffu, mx, o));

        float e0 = expf(lp0 - mx), e1 = expf(lp1 - mx);
        float se  = e0 + e1;
        float ser = er0 + er1;
        float sep = er0 * e0 + er1 * e1;
        #pragma unroll
        for (int o = 16; o; o >>= 1) {
            se  += __shfl_xor_sync(0xffffffffu, se,  o);
            ser += __shfl_xor_sync(0xffffffffu, ser, o);
            sep += __shfl_xor_sync(0xffffffffu, sep, o);
        }
        if (lane == 0)
            d_partial[b] = (double)sep / (double)se - (double)ser / 64.0;
    }
    __syncthreads();

    // ---- last-block ticket: global mean ----
    if (tid == 0) {
        __threadfence();
        unsigned tk = atomicAdd(&d_ticket, 1u);
        sLast = (tk == NBATCH - 1);
    }
    __syncthreads();
    if (sLast) {
        __threadfence();
        if (tid < NBATCH) sSum[tid] = d_partial[tid];
        __syncthreads();
        #pragma unroll
        for (int o = 64; o; o >>= 1) {
            if (tid < o) sSum[tid] += sSum[tid + o];
            __syncthreads();
        }
        if (tid == 0) {
            out[0] = (float)(sSum[0] / (double)NSEQ);
            d_ticket = 0;               // reset for next graph replay
        }
    }
}

// ---------------------------------------------------------------------------
extern "C" void kernel_launch(void* const* d_in, const int* in_sizes, int n_in,
                              void* d_out, int out_size) {
    const float* logp = (const float*)d_in[0];  // (128,64) f32
    const int*   ref  = (const int*)d_in[1];    // (256,128) i32
    const int*   hyp  = (const int*)d_in[2];    // (256,128,64) i32
    float* out = (float*)d_out;

    mer_loss_kernel<<<NBATCH, 256>>>(hyp, ref, logp, out);
}